// round 10
// baseline (speedup 1.0000x reference)
#include <cuda_runtime.h>
#include <cuda_fp16.h>
#include <stdint.h>

#define M_ROWS   8192
#define DM       768
#define NF       16384
#define TOPK     64
#define TOPC     128
#define KDIM     768
#define SURV_CAP 4096

// ---------------- scratch (__device__ globals; no allocs) ----------------
__device__ __align__(256) __half g_A[M_ROWS * KDIM];   // 12.6 MB
__device__ __align__(256) __half g_B[NF     * KDIM];   // 25.2 MB

// ---------------- helpers ----------------
__device__ __forceinline__ uint32_t smem_u32(const void* p) {
    uint32_t a;
    asm("{ .reg .u64 t; cvta.to.shared.u64 t, %1; cvt.u32.u64 %0, t; }" : "=r"(a) : "l"(p));
    return a;
}
__device__ __forceinline__ void cp_async16(uint32_t dst, const void* src) {
    asm volatile("cp.async.cg.shared.global [%0], [%1], 16;" :: "r"(dst), "l"(src));
}
#define CP_COMMIT() asm volatile("cp.async.commit_group;" ::: "memory")
#define CP_WAIT(n)  asm volatile("cp.async.wait_group %0;" :: "n"(n) : "memory")

__device__ __forceinline__ void mma16816(float* c,
                                         uint32_t a0, uint32_t a1, uint32_t a2, uint32_t a3,
                                         uint32_t b0, uint32_t b1) {
    asm volatile("mma.sync.aligned.m16n8k16.row.col.f32.f16.f16.f32 "
        "{%0,%1,%2,%3}, {%4,%5,%6,%7}, {%8,%9}, {%0,%1,%2,%3};"
        : "+f"(c[0]), "+f"(c[1]), "+f"(c[2]), "+f"(c[3])
        : "r"(a0), "r"(a1), "r"(a2), "r"(a3), "r"(b0), "r"(b1));
}
__device__ __forceinline__ void ldsm_x4(uint32_t& r0, uint32_t& r1,
                                        uint32_t& r2, uint32_t& r3, uint32_t addr) {
    asm volatile("ldmatrix.sync.aligned.m8n8.x4.shared.b16 {%0,%1,%2,%3}, [%4];"
        : "=r"(r0), "=r"(r1), "=r"(r2), "=r"(r3) : "r"(addr));
}
__device__ __forceinline__ void ldsm_x2(uint32_t& r0, uint32_t& r1, uint32_t addr) {
    asm volatile("ldmatrix.sync.aligned.m8n8.x2.shared.b16 {%0,%1}, [%2];"
        : "=r"(r0), "=r"(r1) : "r"(addr));
}

// match-aggregated smem histogram add (sentinel 0xffffffff = inactive)
__device__ __forceinline__ void hadd(unsigned* myh, unsigned bin, int lane) {
    unsigned peers = __match_any_sync(0xffffffffu, bin);
    if (bin != 0xffffffffu && lane == (__ffs(peers) - 1))
        atomicAdd(&myh[bin], (unsigned)__popc(peers));
}

// ============================================================
// convert: fp32 -> fp16, vectorized x4
// ============================================================
__global__ void convert_x_kernel(const float* __restrict__ x) {
    int i = blockIdx.x * blockDim.x + threadIdx.x;
    if (i >= M_ROWS * KDIM / 4) return;
    float4 v = ((const float4*)x)[i];
    ((__half2*)g_A)[i * 2]     = __floats2half2_rn(v.x, v.y);
    ((__half2*)g_A)[i * 2 + 1] = __floats2half2_rn(v.z, v.w);
}
__global__ void convert_w_kernel(const float* __restrict__ w) {
    int i = blockIdx.x * blockDim.x + threadIdx.x;
    if (i >= NF * KDIM / 4) return;
    float4 v = ((const float4*)w)[i];
    ((__half2*)g_B)[i * 2]     = __floats2half2_rn(v.x, v.y);
    ((__half2*)g_B)[i * 2 + 1] = __floats2half2_rn(v.z, v.w);
}

// ============================================================
// mma.sync fp16 GEMM, watertight 4-stage pipeline + ldmatrix
// ============================================================
#define BM 128
#define BN 128
#define BK 32
#define STAGES 4
#define ROWB 80
#define STG (256 * ROWB)
#define GEMM_SMEM (STAGES * STG)       // 81920 B
#define KITERS (KDIM / BK)             // 24

__global__ __launch_bounds__(256, 2)
void gemm_mma_kernel(const float* __restrict__ bias, float* __restrict__ pre) {
    extern __shared__ char sm[];
    const uint32_t sb = smem_u32(sm);
    const int tid = threadIdx.x;
    const int wid = tid >> 5;
    const int lane = tid & 31;
    const int g   = lane >> 2;
    const int tig = lane & 3;
    const int bm = blockIdx.x * BM;
    const int bn = blockIdx.y * BN;
    const int wm = (wid >> 2) * 64;
    const int wn = (wid & 3) * 32;

    const __half* Ag = g_A + (size_t)bm * KDIM;
    const __half* Bg = g_B + (size_t)bn * KDIM;

    float acc[4][4][4];
#pragma unroll
    for (int mi = 0; mi < 4; mi++)
#pragma unroll
        for (int ni = 0; ni < 4; ni++)
#pragma unroll
            for (int q = 0; q < 4; q++) acc[mi][ni][q] = 0.f;

    const int lr0 = tid >> 2;
    const int lr1 = (tid + 256) >> 2;
    const int lc  = tid & 3;

    auto issue = [&](int s) {
        const uint32_t base = sb + (s % STAGES) * STG;
        const size_t k0 = (size_t)s * BK;
        cp_async16(base + lr0 * ROWB + lc * 16, Ag + (size_t)lr0 * KDIM + k0 + lc * 8);
        cp_async16(base + lr1 * ROWB + lc * 16, Ag + (size_t)lr1 * KDIM + k0 + lc * 8);
        const uint32_t bb = base + 128 * ROWB;
        cp_async16(bb + lr0 * ROWB + lc * 16, Bg + (size_t)lr0 * KDIM + k0 + lc * 8);
        cp_async16(bb + lr1 * ROWB + lc * 16, Bg + (size_t)lr1 * KDIM + k0 + lc * 8);
    };

    issue(0); CP_COMMIT();
    issue(1); CP_COMMIT();
    issue(2); CP_COMMIT();

    // ldmatrix per-lane address components
    const uint32_t a_lrow = (uint32_t)(lane & 15) * ROWB + ((lane >> 4) & 1) * 16;
    const uint32_t b_lrow = (uint32_t)(lane & 7)  * ROWB + ((lane >> 3) & 1) * 16;

    for (int kb = 0; kb < KITERS; kb++) {
        if (kb + 3 < KITERS) issue(kb + 3);
        CP_COMMIT();
        CP_WAIT(3);
        __syncthreads();

        const uint32_t abase = sb + (kb % STAGES) * STG;
        const uint32_t bbase = abase + 128 * ROWB;
#pragma unroll
        for (int kk = 0; kk < 2; kk++) {
            uint32_t bfr[4][2];
#pragma unroll
            for (int ni = 0; ni < 4; ni++)
                ldsm_x2(bfr[ni][0], bfr[ni][1],
                        bbase + (wn + ni * 8) * ROWB + kk * 32 + b_lrow);
#pragma unroll
            for (int mi = 0; mi < 4; mi++) {
                uint32_t a0, a1, a2, a3;
                ldsm_x4(a0, a1, a2, a3,
                        abase + (wm + mi * 16) * ROWB + kk * 32 + a_lrow);
#pragma unroll
                for (int ni = 0; ni < 4; ni++)
                    mma16816(acc[mi][ni], a0, a1, a2, a3, bfr[ni][0], bfr[ni][1]);
            }
        }
        __syncthreads();
    }

#pragma unroll
    for (int ni = 0; ni < 4; ni++) {
        const int col = bn + wn + ni * 8 + tig * 2;
        float2 bz = *(const float2*)(bias + col);
#pragma unroll
        for (int mi = 0; mi < 4; mi++) {
            const int r0 = bm + wm + mi * 16 + g;
            float2 v0, v1;
            v0.x = acc[mi][ni][0] + bz.x; v0.y = acc[mi][ni][1] + bz.y;
            v1.x = acc[mi][ni][2] + bz.x; v1.y = acc[mi][ni][3] + bz.y;
            *(float2*)(pre + (size_t)r0 * NF + col)       = v0;
            *(float2*)(pre + (size_t)(r0 + 8) * NF + col) = v1;
        }
    }
}

// ============================================================
// FUSED post-GEMM (one block/row):
//  p1: float4 load pre -> keys + fused pass-1 hist (match-agg)
//  p2: warp0 pivot scan; compact survivors (key,idx16); direct
//      candidates for bins > pivot-byte
//  p3: passes 2-4 over survivors only (fallback: full su scan)
//  p4: rescore (warps 0-3, exact fmaf chain) || zero su (4-7)
//  p5: rank + stage codes row; stream out; sparse decode
// ============================================================
#define OFF_SU     0
#define OFF_XS     65536
#define OFF_WH     (OFF_XS + DM * 4)               // 68608, 8x256 u32
#define OFF_SKEY   (OFF_WH + 8 * 256 * 4)          // 76800, 4096 u32
#define OFF_SIDX16 (OFF_SKEY + SURV_CAP * 4)       // 93184, 4096 u16
#define OFF_SVAL   (OFF_SIDX16 + SURV_CAP * 2)     // 101376
#define OFF_SIDX   (OFF_SVAL + TOPC * 4)           // 101888
#define OFF_CIDX   (OFF_SIDX + TOPC * 4)           // 102400
#define OFF_TKI    (OFF_CIDX + TOPC * 4)           // 102912
#define OFF_TKV    (OFF_TKI + TOPK * 4)            // 103168
#define FUSE_SMEM  (OFF_TKV + TOPK * 4)            // 103424

__global__ __launch_bounds__(256, 2)
void postgemm_kernel(const float* __restrict__ pre,
                     const float* __restrict__ x,
                     const float* __restrict__ Wenc,
                     const float* __restrict__ benc,
                     const float* __restrict__ Dm,
                     float* __restrict__ codes,
                     float* __restrict__ recon) {
    extern __shared__ char smraw[];
    unsigned*       su     = (unsigned*)(smraw + OFF_SU);
    float*          xs     = (float*)   (smraw + OFF_XS);
    unsigned*       whist  = (unsigned*)(smraw + OFF_WH);
    unsigned*       skey   = (unsigned*)(smraw + OFF_SKEY);
    unsigned short* sidx16 = (unsigned short*)(smraw + OFF_SIDX16);
    float*          sval   = (float*)   (smraw + OFF_SVAL);
    int*            sidx   = (int*)     (smraw + OFF_SIDX);
    int*            cidx   = (int*)     (smraw + OFF_CIDX);
    int*            stki   = (int*)     (smraw + OFF_TKI);
    float*          stkv   = (float*)   (smraw + OFF_TKV);
    __shared__ unsigned s_prefix, s_want, s_cnt, s_scnt;

    const int row = blockIdx.x;
    const int tid = threadIdx.x;
    const int wid = tid >> 5;
    const int lane = tid & 31;
    unsigned* myh = whist + (wid << 8);

    // ---- phase 1: zero hists, then fused load + keys + pass-1 hist ----
#pragma unroll
    for (int h = 0; h < 8; h++) whist[h * 256 + tid] = 0u;
    if (tid == 0) { s_prefix = 0u; s_want = TOPC; s_cnt = 0u; s_scnt = 0u; }
    __syncthreads();

    {
        const float4* p4 = (const float4*)(pre + (size_t)row * NF);
        uint4* su4 = (uint4*)su;
        for (int i = tid; i < NF / 4; i += 256) {
            float4 v = p4[i];
            unsigned b0 = __float_as_uint(v.x), b1 = __float_as_uint(v.y);
            unsigned b2 = __float_as_uint(v.z), b3 = __float_as_uint(v.w);
            unsigned k0 = (b0 & 0x80000000u) ? ~b0 : (b0 | 0x80000000u);
            unsigned k1 = (b1 & 0x80000000u) ? ~b1 : (b1 | 0x80000000u);
            unsigned k2 = (b2 & 0x80000000u) ? ~b2 : (b2 | 0x80000000u);
            unsigned k3 = (b3 & 0x80000000u) ? ~b3 : (b3 | 0x80000000u);
            su4[i] = make_uint4(k0, k1, k2, k3);
            hadd(myh, k0 >> 24, lane);
            hadd(myh, k1 >> 24, lane);
            hadd(myh, k2 >> 24, lane);
            hadd(myh, k3 >> 24, lane);
        }
        for (int i = tid; i < DM; i += 256) xs[i] = x[(size_t)row * DM + i];
    }
    __syncthreads();

    // ---- pivot scan helper (merge 8 hists + warp0 scan) ----
    auto pivot_scan = [&]() {
        unsigned tot = 0;
#pragma unroll
        for (int h = 0; h < 8; h++) tot += whist[h * 256 + tid];
        whist[tid] = tot;                  // column tid: private read->write
        __syncthreads();
        if (wid == 0) {
            const unsigned want = s_want;
            const unsigned pref = s_prefix;
            unsigned c[8], local = 0;
#pragma unroll
            for (int t = 0; t < 8; t++) { c[t] = whist[255 - (lane * 8 + t)]; local += c[t]; }
            unsigned incl = local;
#pragma unroll
            for (int o = 1; o < 32; o <<= 1) {
                unsigned n = __shfl_up_sync(0xffffffffu, incl, o);
                if (lane >= o) incl += n;
            }
            unsigned run = incl - local;
#pragma unroll
            for (int t = 0; t < 8; t++) {
                if (run < want && want <= run + c[t]) {
                    s_prefix = (pref << 8) | (unsigned)(255 - (lane * 8 + t));
                    s_want = want - run;
                }
                run += c[t];
            }
        }
        __syncthreads();
    };

    pivot_scan();                          // pass 1 pivot byte

    // ---- phase 2: compaction (single su scan) ----
    const unsigned pv1 = s_prefix;         // 8-bit
    for (int i = tid; i < NF; i += 256) {
        unsigned u = su[i];
        unsigned b = u >> 24;
        if (b > pv1) {
            unsigned s = atomicAdd(&s_cnt, 1u);   // < TOPC by pivot invariant
            cidx[s] = i;
        } else if (b == pv1) {
            unsigned s = atomicAdd(&s_scnt, 1u);
            if (s < SURV_CAP) { skey[s] = u; sidx16[s] = (unsigned short)i; }
        }
    }
    __syncthreads();
    const bool ovf = (s_scnt > SURV_CAP);
    const unsigned scnt = ovf ? 0u : s_scnt;
    const unsigned srnd = (scnt + 255u) & ~255u;

    // ---- phase 3: passes 2-4 over survivors (or su fallback) ----
#pragma unroll
    for (int shift = 16; shift >= 0; shift -= 8) {
#pragma unroll
        for (int h = 0; h < 8; h++) whist[h * 256 + tid] = 0u;
        __syncthreads();
        const unsigned pref = s_prefix;
        if (!ovf) {
            for (unsigned i = tid; i < srnd; i += 256) {
                unsigned binsel = 0xffffffffu;
                if (i < scnt) {
                    unsigned u = skey[i];
                    if ((u >> (shift + 8)) == pref) binsel = (u >> shift) & 255u;
                }
                hadd(myh, binsel, lane);
            }
        } else {
            for (int i = tid; i < NF; i += 256) {
                unsigned u = su[i];
                unsigned binsel = ((u >> (shift + 8)) == pref) ? ((u >> shift) & 255u)
                                                               : 0xffffffffu;
                hadd(myh, binsel, lane);
            }
        }
        __syncthreads();
        pivot_scan();
    }

    // ---- final candidate collection ----
    const unsigned pivot = s_prefix;
    if (!ovf) {
        for (unsigned i = tid; i < scnt; i += 256) {
            if (skey[i] >= pivot) {
                unsigned s = atomicAdd(&s_cnt, 1u);
                if (s < TOPC) cidx[s] = (int)sidx16[i];
            }
        }
    } else {
        if (tid == 0) s_cnt = 0u;
        __syncthreads();
        for (int i = tid; i < NF; i += 256) {
            if (su[i] >= pivot) {
                unsigned s = atomicAdd(&s_cnt, 1u);
                if (s < TOPC) cidx[s] = i;
            }
        }
    }
    __syncthreads();

    // ---- phase 4: rescore (warps 0-3) || zero su (warps 4-7) ----
    if (tid < TOPC) {
        const int idx = cidx[tid];
        const float4* wr = (const float4*)(Wenc + (size_t)idx * DM);
        float acc = 0.f;
#pragma unroll 4
        for (int q = 0; q < DM / 4; q++) {
            float4 w = wr[q];
            acc = fmaf(xs[q * 4 + 0], w.x, acc);
            acc = fmaf(xs[q * 4 + 1], w.y, acc);
            acc = fmaf(xs[q * 4 + 2], w.z, acc);
            acc = fmaf(xs[q * 4 + 3], w.w, acc);
        }
        sval[tid] = acc + benc[idx];
        sidx[tid] = idx;
    } else {
        uint4 z = make_uint4(0u, 0u, 0u, 0u);
        uint4* su4 = (uint4*)su;
        for (int i = tid - TOPC; i < NF / 4; i += 256 - TOPC) su4[i] = z;
    }
    __syncthreads();

    // ---- phase 5: rank + stage top-64 into su (codes row) ----
    if (tid < TOPC) {
        float v = sval[tid];
        int myi = sidx[tid];
        int rank = 0;
#pragma unroll 8
        for (int j = 0; j < TOPC; j++) {
            float vj = sval[j];
            rank += (vj > v) || (vj == v && sidx[j] < myi);
        }
        if (rank < TOPK) {
            stki[rank] = myi;
            stkv[rank] = v;
            su[myi] = __float_as_uint(v);
        }
    }
    __syncthreads();

    // ---- phase 6: stream codes row + sparse decode ----
    {
        float4* crow = (float4*)(codes + (size_t)row * NF);
        const float4* su4 = (const float4*)su;
        for (int i = tid; i < NF / 4; i += 256) crow[i] = su4[i];
    }
    {
        const int c0 = tid, c1 = tid + 256, c2 = tid + 512;
        float a0 = 0.f, a1 = 0.f, a2 = 0.f;
#pragma unroll 4
        for (int k = 0; k < TOPK; k++) {
            const float* dr = Dm + (size_t)stki[k] * DM;
            float v = stkv[k];
            a0 += v * dr[c0]; a1 += v * dr[c1]; a2 += v * dr[c2];
        }
        float* r = recon + (size_t)row * DM;
        r[c0] = a0; r[c1] = a1; r[c2] = a2;
    }
}

// ============================================================
// launch
// ============================================================
extern "C" void kernel_launch(void* const* d_in, const int* in_sizes, int n_in,
                              void* d_out, int out_size) {
    const float* x    = (const float*)d_in[0];
    const float* Wenc = (const float*)d_in[1];
    const float* benc = (const float*)d_in[2];
    const float* Dm   = (const float*)d_in[3];

    float* out   = (float*)d_out;
    float* recon = out;
    float* codes = out + (size_t)M_ROWS * DM;
    float* pre   = codes + (size_t)M_ROWS * NF;

    cudaFuncSetAttribute(gemm_mma_kernel,
                         cudaFuncAttributeMaxDynamicSharedMemorySize, GEMM_SMEM);
    cudaFuncSetAttribute(postgemm_kernel,
                         cudaFuncAttributeMaxDynamicSharedMemorySize, FUSE_SMEM);

    convert_x_kernel<<<(M_ROWS * KDIM / 4 + 255) / 256, 256>>>(x);
    convert_w_kernel<<<(NF * KDIM / 4 + 255) / 256, 256>>>(Wenc);
    {
        dim3 grid(M_ROWS / BM, NF / BN);
        gemm_mma_kernel<<<grid, 256, GEMM_SMEM>>>(benc, pre);
    }
    postgemm_kernel<<<M_ROWS, 256, FUSE_SMEM>>>(pre, x, Wenc, benc, Dm,
                                                codes, recon);
}

// round 11
// speedup vs baseline: 1.3199x; 1.3199x over previous
#include <cuda_runtime.h>
#include <cuda_fp16.h>
#include <stdint.h>

#define M_ROWS   8192
#define DM       768
#define NF       16384
#define TOPK     64
#define TOPC     128
#define KDIM     768
#define CAND_MAX 1024

// ---------------- scratch (__device__ globals; no allocs) ----------------
__device__ __align__(256) __half g_A[M_ROWS * KDIM];   // 12.6 MB
__device__ __align__(256) __half g_B[NF     * KDIM];   // 25.2 MB

// ---------------- helpers ----------------
__device__ __forceinline__ uint32_t smem_u32(const void* p) {
    uint32_t a;
    asm("{ .reg .u64 t; cvta.to.shared.u64 t, %1; cvt.u32.u64 %0, t; }" : "=r"(a) : "l"(p));
    return a;
}
__device__ __forceinline__ void cp_async16(uint32_t dst, const void* src) {
    asm volatile("cp.async.cg.shared.global [%0], [%1], 16;" :: "r"(dst), "l"(src));
}
#define CP_COMMIT() asm volatile("cp.async.commit_group;" ::: "memory")
#define CP_WAIT(n)  asm volatile("cp.async.wait_group %0;" :: "n"(n) : "memory")

__device__ __forceinline__ void mma16816(float* c,
                                         uint32_t a0, uint32_t a1, uint32_t a2, uint32_t a3,
                                         uint32_t b0, uint32_t b1) {
    asm volatile("mma.sync.aligned.m16n8k16.row.col.f32.f16.f16.f32 "
        "{%0,%1,%2,%3}, {%4,%5,%6,%7}, {%8,%9}, {%0,%1,%2,%3};"
        : "+f"(c[0]), "+f"(c[1]), "+f"(c[2]), "+f"(c[3])
        : "r"(a0), "r"(a1), "r"(a2), "r"(a3), "r"(b0), "r"(b1));
}
__device__ __forceinline__ unsigned fkey(unsigned b) {
    return (b & 0x80000000u) ? ~b : (b | 0x80000000u);
}

// ============================================================
// convert: fp32 -> fp16, vectorized x4
// ============================================================
__global__ void convert_x_kernel(const float* __restrict__ x) {
    int i = blockIdx.x * blockDim.x + threadIdx.x;
    if (i >= M_ROWS * KDIM / 4) return;
    float4 v = ((const float4*)x)[i];
    ((__half2*)g_A)[i * 2]     = __floats2half2_rn(v.x, v.y);
    ((__half2*)g_A)[i * 2 + 1] = __floats2half2_rn(v.z, v.w);
}
__global__ void convert_w_kernel(const float* __restrict__ w) {
    int i = blockIdx.x * blockDim.x + threadIdx.x;
    if (i >= NF * KDIM / 4) return;
    float4 v = ((const float4*)w)[i];
    ((__half2*)g_B)[i * 2]     = __floats2half2_rn(v.x, v.y);
    ((__half2*)g_B)[i * 2 + 1] = __floats2half2_rn(v.z, v.w);
}

// ============================================================
// mma.sync fp16 GEMM — exact validated R9 version (746us)
// ============================================================
#define BM 128
#define BN 128
#define BK 32
#define STAGES 4
#define ROWB 80
#define STG (256 * ROWB)
#define GEMM_SMEM (STAGES * STG)       // 81920 B
#define KITERS (KDIM / BK)             // 24

__global__ __launch_bounds__(256, 2)
void gemm_mma_kernel(const float* __restrict__ bias, float* __restrict__ pre) {
    extern __shared__ char sm[];
    const uint32_t sb = smem_u32(sm);
    const int tid = threadIdx.x;
    const int wid = tid >> 5;
    const int lane = tid & 31;
    const int g   = lane >> 2;
    const int tig = lane & 3;
    const int bm = blockIdx.x * BM;
    const int bn = blockIdx.y * BN;
    const int wm = (wid >> 2) * 64;
    const int wn = (wid & 3) * 32;

    const __half* Ag = g_A + (size_t)bm * KDIM;
    const __half* Bg = g_B + (size_t)bn * KDIM;

    float acc[4][4][4];
#pragma unroll
    for (int mi = 0; mi < 4; mi++)
#pragma unroll
        for (int ni = 0; ni < 4; ni++)
#pragma unroll
            for (int q = 0; q < 4; q++) acc[mi][ni][q] = 0.f;

    const int lr0 = tid >> 2;
    const int lr1 = (tid + 256) >> 2;
    const int lc  = tid & 3;

    auto issue = [&](int s) {
        const uint32_t base = sb + (s % STAGES) * STG;
        const size_t k0 = (size_t)s * BK;
        cp_async16(base + lr0 * ROWB + lc * 16, Ag + (size_t)lr0 * KDIM + k0 + lc * 8);
        cp_async16(base + lr1 * ROWB + lc * 16, Ag + (size_t)lr1 * KDIM + k0 + lc * 8);
        const uint32_t bb = base + 128 * ROWB;
        cp_async16(bb + lr0 * ROWB + lc * 16, Bg + (size_t)lr0 * KDIM + k0 + lc * 8);
        cp_async16(bb + lr1 * ROWB + lc * 16, Bg + (size_t)lr1 * KDIM + k0 + lc * 8);
    };

    issue(0); CP_COMMIT();
    issue(1); CP_COMMIT();
    issue(2); CP_COMMIT();

    for (int kb = 0; kb < KITERS; kb++) {
        if (kb + 3 < KITERS) issue(kb + 3);
        CP_COMMIT();
        CP_WAIT(3);
        __syncthreads();

        const char* Abuf = sm + (kb % STAGES) * STG;
        const char* Bbuf = Abuf + 128 * ROWB;
#pragma unroll
        for (int kk = 0; kk < 2; kk++) {
            uint32_t bfr[4][2];
#pragma unroll
            for (int ni = 0; ni < 4; ni++) {
                const char* bp = Bbuf + (wn + ni * 8 + g) * ROWB + kk * 32 + tig * 4;
                bfr[ni][0] = *(const uint32_t*)bp;
                bfr[ni][1] = *(const uint32_t*)(bp + 16);
            }
#pragma unroll
            for (int mi = 0; mi < 4; mi++) {
                const char* ap0 = Abuf + (wm + mi * 16 + g) * ROWB + kk * 32 + tig * 4;
                const char* ap1 = ap0 + 8 * ROWB;
                uint32_t a0 = *(const uint32_t*)ap0;
                uint32_t a1 = *(const uint32_t*)ap1;
                uint32_t a2 = *(const uint32_t*)(ap0 + 16);
                uint32_t a3 = *(const uint32_t*)(ap1 + 16);
#pragma unroll
                for (int ni = 0; ni < 4; ni++)
                    mma16816(acc[mi][ni], a0, a1, a2, a3, bfr[ni][0], bfr[ni][1]);
            }
        }
        __syncthreads();
    }

#pragma unroll
    for (int ni = 0; ni < 4; ni++) {
        const int col = bn + wn + ni * 8 + tig * 2;
        float2 bz = *(const float2*)(bias + col);
#pragma unroll
        for (int mi = 0; mi < 4; mi++) {
            const int r0 = bm + wm + mi * 16 + g;
            float2 v0, v1;
            v0.x = acc[mi][ni][0] + bz.x; v0.y = acc[mi][ni][1] + bz.y;
            v1.x = acc[mi][ni][2] + bz.x; v1.y = acc[mi][ni][3] + bz.y;
            *(float2*)(pre + (size_t)r0 * NF + col)       = v0;
            *(float2*)(pre + (size_t)(r0 + 8) * NF + col) = v1;
        }
    }
}

// ============================================================
// FUSED post-GEMM v3 (one block/row, ~32KB smem, high occ):
//   p1: stream pre (float4), 12-bit key hist (4096 bins)
//   p2: hierarchical pivot scan -> pivot bin (+rare lvl-2 refine)
//   p3: re-stream pre, collect candidate indices (>= bin floor)
//   p4: exact fp32 rescore (ascending-k fmaf chain, validated)
//   p5: zero-stream codes row; rank; scatter winners
//   p6: sparse decode
// ============================================================
__global__ __launch_bounds__(256)
void postgemm_kernel(const float* __restrict__ pre,
                     const float* __restrict__ x,
                     const float* __restrict__ Wenc,
                     const float* __restrict__ benc,
                     const float* __restrict__ Dm,
                     float* __restrict__ codes,
                     float* __restrict__ recon) {
    __shared__ float    xs[DM];
    __shared__ unsigned hist[4096];
    __shared__ float    sval[CAND_MAX];
    __shared__ int      sidxA[CAND_MAX];
    __shared__ int      cidx[CAND_MAX];
    __shared__ int      stki[TOPK];
    __shared__ float    stkv[TOPK];
    __shared__ unsigned wsum[8];
    __shared__ unsigned s_pv, s_chi, s_pv2, s_cnt;
    __shared__ int      s_lvl2;

    const int row = blockIdx.x;
    const int tid = threadIdx.x;
    const int wid = tid >> 5;
    const int lane = tid & 31;
    const float4* p4 = (const float4*)(pre + (size_t)row * NF);

    // ---- p1: zero hist; stream pre -> 12-bit hist; load x ----
#pragma unroll
    for (int q = 0; q < 16; q++) hist[tid + q * 256] = 0u;
    if (tid == 0) { s_cnt = 0u; s_lvl2 = 0; }
    __syncthreads();

    for (int i = tid; i < NF / 4; i += 256) {
        float4 v = p4[i];
        atomicAdd(&hist[fkey(__float_as_uint(v.x)) >> 20], 1u);
        atomicAdd(&hist[fkey(__float_as_uint(v.y)) >> 20], 1u);
        atomicAdd(&hist[fkey(__float_as_uint(v.z)) >> 20], 1u);
        atomicAdd(&hist[fkey(__float_as_uint(v.w)) >> 20], 1u);
    }
    for (int i = tid; i < DM; i += 256) xs[i] = x[(size_t)row * DM + i];
    __syncthreads();

    // ---- pivot scan over 4096 bins, descending; want = TOPC ----
    auto pivot4096 = [&](unsigned want, unsigned* out_pv, unsigned* out_chi) {
        unsigned h[16], csum = 0;
        const int hi = 4095 - 16 * tid;
#pragma unroll
        for (int q = 0; q < 16; q++) { h[q] = hist[hi - q]; csum += h[q]; }
        unsigned incl = csum;
#pragma unroll
        for (int o = 1; o < 32; o <<= 1) {
            unsigned n = __shfl_up_sync(0xffffffffu, incl, o);
            if (lane >= o) incl += n;
        }
        if (lane == 31) wsum[wid] = incl;
        __syncthreads();
        if (wid == 0 && lane < 8) {
            unsigned w = wsum[lane];
#pragma unroll
            for (int o = 1; o < 8; o <<= 1) {
                unsigned n = __shfl_up_sync(0x000000ffu, w, o);
                if (lane >= o) w += n;
            }
            wsum[lane] = w;
        }
        __syncthreads();
        incl += (wid > 0 ? wsum[wid - 1] : 0u);
        unsigned excl = incl - csum;
        if (excl < want && want <= incl) {
            unsigned run = excl;
#pragma unroll
            for (int q = 0; q < 16; q++) {
                if (run < want && want <= run + h[q]) {
                    *out_pv = (unsigned)(hi - q);
                    *out_chi = run;
                }
                run += h[q];
            }
        }
        __syncthreads();
    };

    pivot4096(TOPC, &s_pv, &s_chi);
    const unsigned pv1 = s_pv;
    const unsigned chi = s_chi;          // count strictly above pivot bin
    const unsigned cb  = hist[pv1];      // pivot-bin count

    // ---- rare level-2 refinement if pivot bin too fat ----
    if (chi + cb > CAND_MAX) {
        __syncthreads();
#pragma unroll
        for (int q = 0; q < 16; q++) hist[tid + q * 256] = 0u;
        __syncthreads();
        for (int i = tid; i < NF; i += 256) {
            unsigned k = fkey(__float_as_uint(pre[(size_t)row * NF + i]));
            if ((k >> 20) == pv1) atomicAdd(&hist[(k >> 8) & 0xfffu], 1u);
        }
        __syncthreads();
        pivot4096(TOPC - chi, &s_pv2, &s_chi);
        if (tid == 0) s_lvl2 = 1;
        __syncthreads();
    }
    const int lvl2 = s_lvl2;
    const unsigned pv2 = lvl2 ? s_pv2 : 0u;

    // ---- p3: collect candidates ----
    for (int i = tid; i < NF; i += 256) {
        unsigned k = fkey(__float_as_uint(pre[(size_t)row * NF + i]));
        unsigned b = k >> 20;
        bool take = (b > pv1) ||
                    (b == pv1 && (!lvl2 || ((k >> 8) & 0xfffu) >= pv2));
        if (take) {
            unsigned slot = atomicAdd(&s_cnt, 1u);
            if (slot < CAND_MAX) cidx[slot] = i;
        }
    }
    __syncthreads();
    const int C = (int)min(s_cnt, (unsigned)CAND_MAX);

    // ---- p4: exact fp32 rescore (validated ascending-k chain) ----
    for (int j = tid; j < C; j += 256) {
        const int idx = cidx[j];
        const float4* wr = (const float4*)(Wenc + (size_t)idx * DM);
        float acc = 0.f;
#pragma unroll 4
        for (int q = 0; q < DM / 4; q++) {
            float4 w = wr[q];
            acc = fmaf(xs[q * 4 + 0], w.x, acc);
            acc = fmaf(xs[q * 4 + 1], w.y, acc);
            acc = fmaf(xs[q * 4 + 2], w.z, acc);
            acc = fmaf(xs[q * 4 + 3], w.w, acc);
        }
        sval[j] = acc + benc[idx];
        sidxA[j] = idx;
    }

    // ---- p5a: zero-stream codes row (no staging buffer) ----
    {
        float4* crow = (float4*)(codes + (size_t)row * NF);
        float4 z = make_float4(0.f, 0.f, 0.f, 0.f);
        for (int i = tid; i < NF / 4; i += 256) crow[i] = z;
    }
    __syncthreads();

    // ---- p5b: rank (idx tiebreak) + scatter winners ----
    for (int j = tid; j < C; j += 256) {
        float v = sval[j];
        int myi = sidxA[j];
        int rank = 0;
        for (int t = 0; t < C; t++) {
            float vt = sval[t];
            rank += (vt > v) || (vt == v && sidxA[t] < myi);
        }
        if (rank < TOPK) {
            stki[rank] = myi;
            stkv[rank] = v;
            codes[(size_t)row * NF + myi] = v;
        }
    }
    __syncthreads();

    // ---- p6: sparse decode ----
    {
        const int c0 = tid, c1 = tid + 256, c2 = tid + 512;
        float a0 = 0.f, a1 = 0.f, a2 = 0.f;
#pragma unroll 4
        for (int k = 0; k < TOPK; k++) {
            const float* dr = Dm + (size_t)stki[k] * DM;
            float v = stkv[k];
            a0 += v * dr[c0]; a1 += v * dr[c1]; a2 += v * dr[c2];
        }
        float* r = recon + (size_t)row * DM;
        r[c0] = a0; r[c1] = a1; r[c2] = a2;
    }
}

// ============================================================
// launch
// ============================================================
extern "C" void kernel_launch(void* const* d_in, const int* in_sizes, int n_in,
                              void* d_out, int out_size) {
    const float* x    = (const float*)d_in[0];
    const float* Wenc = (const float*)d_in[1];
    const float* benc = (const float*)d_in[2];
    const float* Dm   = (const float*)d_in[3];

    float* out   = (float*)d_out;
    float* recon = out;
    float* codes = out + (size_t)M_ROWS * DM;
    float* pre   = codes + (size_t)M_ROWS * NF;

    cudaFuncSetAttribute(gemm_mma_kernel,
                         cudaFuncAttributeMaxDynamicSharedMemorySize, GEMM_SMEM);

    convert_x_kernel<<<(M_ROWS * KDIM / 4 + 255) / 256, 256>>>(x);
    convert_w_kernel<<<(NF * KDIM / 4 + 255) / 256, 256>>>(Wenc);
    {
        dim3 grid(M_ROWS / BM, NF / BN);
        gemm_mma_kernel<<<grid, 256, GEMM_SMEM>>>(benc, pre);
    }
    postgemm_kernel<<<M_ROWS, 256>>>(pre, x, Wenc, benc, Dm, codes, recon);
}